// round 1
// baseline (speedup 1.0000x reference)
#include <cuda_runtime.h>
#include <math.h>

#define B_   8192
#define L_   200
#define S_   81
#define CEN_ 40
#define D_   128
#define H_   4
#define XSZ  (L_*S_)   /* 16200 floats per b */

// ---- scratch (device globals; no allocation allowed) ----
__device__ float g_R[(size_t)B_*H_*L_];      // r vectors  [b][h][l]
__device__ float g_c[(size_t)B_*H_];         // c_h = q_h . bk_h
__device__ float g_central[(size_t)B_*D_];   // central = Wv xs_c + bv
__device__ float g_Y[(size_t)B_*H_*L_];      // y_h[l] = sum_s attn[h,s] xs[s][l]
__device__ float g_sur[(size_t)B_*D_];       // surround

// ============================================================
// kprep: per 64-b tile: gather xs_center, compute Q (=Xc Wq^T + bq),
// central (=Xc Wv^T + bv), then R[b,h,l] = sum_d Wk[h*32+d,l]*Q[b,h*32+d]
// and c[b,h] = q_h . bk_h.
// grid 128, block 256, dyn smem = 26368 floats (105472 B)
// ============================================================
__global__ void __launch_bounds__(256, 2) kprep(
    const float* __restrict__ x,  const float* __restrict__ Wk,
    const float* __restrict__ bk, const float* __restrict__ Wv,
    const float* __restrict__ bv, const float* __restrict__ Wq,
    const float* __restrict__ bq)
{
    extern __shared__ float sm[];
    float* XcT = sm;           // [200][64]  XcT[l*64+bb]
    float* Wb  = sm + 12800;   // [256][53]  chunk of Wq|Wv, row dd, cols kk(0..49)
    const int tid = threadIdx.x;
    const int b0  = blockIdx.x * 64;

    // phase a: gather xs_center (strided)
    for (int idx = tid; idx < 64 * 200; idx += 256) {
        int bb = idx & 63, l = idx >> 6;
        XcT[l * 64 + bb] = x[(size_t)(b0 + bb) * XSZ + l * S_ + CEN_];
    }
    __syncthreads();

    // phase b: 64b x 256d GEMM (d<128 -> Q via Wq, d>=128 -> central via Wv)
    const int bi = tid & 7;    // b-group: b = bi*8 + v
    const int dj = tid >> 3;   // d-group: d = dj*8 + u
    float acc[8][8];
    #pragma unroll
    for (int v = 0; v < 8; v++)
        #pragma unroll
        for (int u = 0; u < 8; u++) acc[v][u] = 0.f;

    const int w = tid >> 5, lane = tid & 31;
    for (int k0 = 0; k0 < 200; k0 += 50) {
        // load 50-wide K chunk of all 256 weight rows (coalesced)
        for (int r = 0; r < 32; r++) {
            int dd = w * 32 + r;
            const float* wr = (dd < 128) ? (Wq + dd * L_) : (Wv + (size_t)(dd - 128) * L_);
            Wb[dd * 53 + lane] = wr[k0 + lane];
            if (lane < 18) Wb[dd * 53 + 32 + lane] = wr[k0 + 32 + lane];
        }
        __syncthreads();
        #pragma unroll 2
        for (int kk = 0; kk < 50; kk++) {
            float4 xa0 = *(const float4*)&XcT[(k0 + kk) * 64 + bi * 8];
            float4 xa1 = *(const float4*)&XcT[(k0 + kk) * 64 + bi * 8 + 4];
            float xa[8] = {xa0.x, xa0.y, xa0.z, xa0.w, xa1.x, xa1.y, xa1.z, xa1.w};
            float wv8[8];
            #pragma unroll
            for (int u = 0; u < 8; u++) wv8[u] = Wb[(dj * 8 + u) * 53 + kk];
            #pragma unroll
            for (int v = 0; v < 8; v++)
                #pragma unroll
                for (int u = 0; u < 8; u++)
                    acc[v][u] += xa[v] * wv8[u];
        }
        __syncthreads();
    }

    // epilogue: Q -> smem QT[d][b] (reuses XcT region), central -> global
    float* QT = sm;  // [128][64]
    if (dj < 16) {
        #pragma unroll
        for (int u = 0; u < 8; u++) {
            int d = dj * 8 + u;
            float bqd = bq[d];
            #pragma unroll
            for (int v = 0; v < 8; v++)
                QT[d * 64 + bi * 8 + v] = acc[v][u] + bqd;
        }
    } else {
        #pragma unroll
        for (int u = 0; u < 8; u++) {
            int d = (dj - 16) * 8 + u;
            float bvd = bv[d];
            #pragma unroll
            for (int v = 0; v < 8; v++)
                g_central[(size_t)(b0 + bi * 8 + v) * D_ + d] = acc[v][u] + bvd;
        }
    }
    __syncthreads();

    // c[b,h] = q_h . bk_h
    {
        int bb = tid & 63, h = tid >> 6;
        float cacc = 0.f;
        for (int dd = 0; dd < 32; dd++)
            cacc += QT[(h * 32 + dd) * 64 + bb] * bk[h * 32 + dd];
        g_c[(size_t)(b0 + bb) * H_ + h] = cacc;
    }

    // phase c: R[b,h,l] = sum_{d<32} Wk[h*32+d, l] * Q[b, h*32+d]
    float* Wkc = sm + 8192;        // [128][100] chunk of Wk columns
    const int bi2 = tid >> 5;      // 0..7: b = bi2*8 + v
    for (int lc = 0; lc < 2; lc++) {
        __syncthreads();
        for (int idx = tid; idx < 12800; idx += 256) {
            int dd = idx / 100, ll = idx - dd * 100;
            Wkc[idx] = Wk[(size_t)dd * L_ + lc * 100 + ll];
        }
        __syncthreads();
        for (int h = 0; h < H_; h++) {
            float acc2[8][4];
            #pragma unroll
            for (int v = 0; v < 8; v++)
                #pragma unroll
                for (int jj = 0; jj < 4; jj++) acc2[v][jj] = 0.f;
            for (int d = 0; d < 32; d++) {
                float4 q0 = *(const float4*)&QT[(h * 32 + d) * 64 + bi2 * 8];
                float4 q1 = *(const float4*)&QT[(h * 32 + d) * 64 + bi2 * 8 + 4];
                float q8[8] = {q0.x, q0.y, q0.z, q0.w, q1.x, q1.y, q1.z, q1.w};
                float wk4[4];
                #pragma unroll
                for (int jj = 0; jj < 4; jj++) {
                    int ll = lane + 32 * jj;
                    wk4[jj] = (ll < 100) ? Wkc[(h * 32 + d) * 100 + ll] : 0.f;
                }
                #pragma unroll
                for (int v = 0; v < 8; v++)
                    #pragma unroll
                    for (int jj = 0; jj < 4; jj++)
                        acc2[v][jj] += q8[v] * wk4[jj];
            }
            #pragma unroll
            for (int jj = 0; jj < 4; jj++) {
                int ll = lane + 32 * jj;
                if (ll < 100) {
                    int l = lc * 100 + ll;
                    #pragma unroll
                    for (int v = 0; v < 8; v++)
                        g_R[(size_t)(b0 + bi2 * 8 + v) * (H_ * L_) + h * L_ + l] = acc2[v][jj];
                }
            }
        }
    }
}

// ============================================================
// kmain: per b: stream x[b] to smem once; scores = (r.xs + c)/sqrt(128)
// (+ center mask); softmax; y_h[l] = sum_s attn*xs -> g_Y.
// grid 8192, block 384, dyn smem = 17328 floats (69312 B)
// ============================================================
__global__ void __launch_bounds__(384) kmain(const float* __restrict__ x)
{
    extern __shared__ float sm[];
    float* xs = sm;             // [200][81]
    float* Rs = sm + 16200;     // 800
    float* cs = Rs + 800;       // 4
    float* sc = cs + 4;         // 324 (scores -> attn in place)
    const int tid = threadIdx.x;
    const int b = blockIdx.x;

    const float4* xb = (const float4*)(x + (size_t)b * XSZ);
    for (int idx = tid; idx < XSZ / 4; idx += 384)
        ((float4*)xs)[idx] = xb[idx];
    for (int idx = tid; idx < 800; idx += 384)
        Rs[idx] = g_R[(size_t)b * 800 + idx];
    if (tid < 4) cs[tid] = g_c[(size_t)b * 4 + tid];
    __syncthreads();

    // scores
    if (tid < 324) {
        int h = tid / 81, s = tid - h * 81;
        const float* rh = Rs + h * L_;
        float a0 = 0.f, a1 = 0.f, a2 = 0.f, a3 = 0.f;
        #pragma unroll 2
        for (int l = 0; l < 200; l += 4) {
            a0 += rh[l    ] * xs[(l    ) * S_ + s];
            a1 += rh[l + 1] * xs[(l + 1) * S_ + s];
            a2 += rh[l + 2] * xs[(l + 2) * S_ + s];
            a3 += rh[l + 3] * xs[(l + 3) * S_ + s];
        }
        float v = ((a0 + a1) + (a2 + a3) + cs[h]) * 0.0883883476483184405f;
        if (s == CEN_) v += -1000000.0f;
        sc[tid] = v;
    }
    __syncthreads();

    // softmax: warp h handles row h
    const int wid = tid >> 5, lane = tid & 31;
    if (wid < 4) {
        float v0 = sc[wid * 81 + lane];
        float v1 = sc[wid * 81 + 32 + lane];
        float v2 = (lane < 17) ? sc[wid * 81 + 64 + lane] : -INFINITY;
        float m = fmaxf(v0, fmaxf(v1, v2));
        #pragma unroll
        for (int o = 16; o > 0; o >>= 1) m = fmaxf(m, __shfl_xor_sync(0xffffffffu, m, o));
        float e0 = expf(v0 - m), e1 = expf(v1 - m);
        float e2 = (lane < 17) ? expf(v2 - m) : 0.f;
        float s3 = e0 + e1 + e2;
        #pragma unroll
        for (int o = 16; o > 0; o >>= 1) s3 += __shfl_xor_sync(0xffffffffu, s3, o);
        float rs = 1.f / s3;
        sc[wid * 81 + lane] = e0 * rs;
        sc[wid * 81 + 32 + lane] = e1 * rs;
        if (lane < 17) sc[wid * 81 + 64 + lane] = e2 * rs;
    }
    __syncthreads();

    // y_h[l] = sum_s attn[h,s]*xs[l][s]
    float* Yb = g_Y + (size_t)b * 800;
    for (int o = tid; o < 800; o += 384) {
        int h = o / 200, l = o - h * 200;
        const float* at = sc + h * 81;
        const float* xr = xs + l * S_;
        float a0 = 0.f, a1 = 0.f, a2 = 0.f;
        #pragma unroll 3
        for (int s = 0; s < 81; s += 3) {
            a0 += at[s    ] * xr[s    ];
            a1 += at[s + 1] * xr[s + 1];
            a2 += at[s + 2] * xr[s + 2];
        }
        Yb[o] = a0 + a1 + a2;
    }
}

// ============================================================
// ksur: surround[b, h*32+d] = sum_l Wv[h*32+d,l]*Y[b,h,l] + bv
// grid (128,4), block 256, dyn smem = 20000 floats (80000 B)
// ============================================================
__global__ void __launch_bounds__(256, 2) ksur(const float* __restrict__ Wv,
                                               const float* __restrict__ bv)
{
    extern __shared__ float sm[];
    float* YT  = sm;            // [200][68] (padded)
    float* Wvs = sm + 13600;    // [32][200]
    const int tid = threadIdx.x;
    const int b0 = blockIdx.x * 64;
    const int h  = blockIdx.y;
    const int lane = tid & 31, w = tid >> 5;

    for (int rb = 0; rb < 8; rb++) {
        int bb = w * 8 + rb;
        const float* ysrc = g_Y + (size_t)(b0 + bb) * 800 + h * 200;
        #pragma unroll
        for (int t = 0; t < 7; t++) {
            int l = lane + 32 * t;
            if (l < 200) YT[l * 68 + bb] = ysrc[l];
        }
    }
    for (int idx = tid; idx < 32 * 200; idx += 256)
        Wvs[idx] = Wv[(size_t)(h * 32) * L_ + idx];
    __syncthreads();

    const int bi = tid & 7;    // b = bi*8 + v
    const int dj = tid >> 3;   // d = dj (0..31)
    float acc[8];
    #pragma unroll
    for (int v = 0; v < 8; v++) acc[v] = 0.f;
    for (int l = 0; l < 200; l++) {
        float wv = Wvs[dj * 200 + l];
        float4 y0 = *(const float4*)&YT[l * 68 + bi * 8];
        float4 y1 = *(const float4*)&YT[l * 68 + bi * 8 + 4];
        acc[0] += wv * y0.x; acc[1] += wv * y0.y; acc[2] += wv * y0.z; acc[3] += wv * y0.w;
        acc[4] += wv * y1.x; acc[5] += wv * y1.y; acc[6] += wv * y1.z; acc[7] += wv * y1.w;
    }
    float bvd = bv[h * 32 + dj];
    #pragma unroll
    for (int v = 0; v < 8; v++)
        g_sur[(size_t)(b0 + bi * 8 + v) * D_ + h * 32 + dj] = acc[v] + bvd;
}

// ============================================================
// kgate: gate = sigmoid((central - surround).Wg + bg); out = central + gate*sur
// grid 1024, block 256 (one warp per b)
// ============================================================
__global__ void __launch_bounds__(256) kgate(const float* __restrict__ Wg,
                                             const float* __restrict__ bg,
                                             float* __restrict__ out)
{
    const int lane = threadIdx.x & 31, w = threadIdx.x >> 5;
    const int b = blockIdx.x * 8 + w;
    float4 c4 = *(const float4*)&g_central[(size_t)b * D_ + lane * 4];
    float4 s4 = *(const float4*)&g_sur[(size_t)b * D_ + lane * 4];
    float4 w4 = *(const float4*)&Wg[lane * 4];
    float dot = (c4.x - s4.x) * w4.x + (c4.y - s4.y) * w4.y +
                (c4.z - s4.z) * w4.z + (c4.w - s4.w) * w4.w;
    #pragma unroll
    for (int o = 16; o > 0; o >>= 1) dot += __shfl_xor_sync(0xffffffffu, dot, o);
    float g = 1.f / (1.f + expf(-(dot + bg[0])));
    float4 o4;
    o4.x = c4.x + g * s4.x; o4.y = c4.y + g * s4.y;
    o4.z = c4.z + g * s4.z; o4.w = c4.w + g * s4.w;
    *(float4*)&out[(size_t)b * D_ + lane * 4] = o4;
}

extern "C" void kernel_launch(void* const* d_in, const int* in_sizes, int n_in,
                              void* d_out, int out_size)
{
    const float* x  = (const float*)d_in[0];
    const float* Wk = (const float*)d_in[1];
    const float* bk = (const float*)d_in[2];
    const float* Wv = (const float*)d_in[3];
    const float* bv = (const float*)d_in[4];
    const float* Wq = (const float*)d_in[5];
    const float* bq = (const float*)d_in[6];
    const float* Wg = (const float*)d_in[7];
    const float* bg = (const float*)d_in[8];
    float* out = (float*)d_out;

    cudaFuncSetAttribute(kprep, cudaFuncAttributeMaxDynamicSharedMemorySize, 105472);
    cudaFuncSetAttribute(kmain, cudaFuncAttributeMaxDynamicSharedMemorySize, 69312);
    cudaFuncSetAttribute(ksur,  cudaFuncAttributeMaxDynamicSharedMemorySize, 80000);

    kprep<<<128, 256, 105472>>>(x, Wk, bk, Wv, bv, Wq, bq);
    kmain<<<8192, 384, 69312>>>(x);
    ksur<<<dim3(128, 4), 256, 80000>>>(Wv, bv);
    kgate<<<1024, 256>>>(Wg, bg, out);
}